// round 3
// baseline (speedup 1.0000x reference)
#include <cuda_runtime.h>

#define TT 64
#define LL 64
#define BB 16
#define HH 256
#define KDIM 512      // 2H
#define ZDIM 1024     // 4H
#define NDIAG (TT + LL - 1)
#define GRID 148
#define NTHREADS 256
#define KC 32
#define NCHUNK (KDIM / KC)   // 16

// Persistent state (device globals: allocation-free scratch)
__device__ float g_c[LL * BB * HH];          // 4 MB
__device__ float g_h[2][LL * BB * HH];       // 8 MB (double-buffered by diagonal parity)
__device__ unsigned g_bar;

__device__ __forceinline__ float sig_(float v)  { return 1.0f / (1.0f + __expf(-v)); }
__device__ __forceinline__ float tanh_(float v) { return 2.0f / (1.0f + __expf(-2.0f * v)) - 1.0f; }

__global__ void init_kernel(const float* __restrict__ init_state) {
    int i = blockIdx.x * blockDim.x + threadIdx.x;
    if (i == 0) g_bar = 0u;
    if (i < LL * BB * HH) {
        int l = i / (BB * HH);
        int r = i - l * (BB * HH);
        g_c[i]    = init_state[(l * 2 + 0) * (BB * HH) + r];
        float h   = init_state[(l * 2 + 1) * (BB * HH) + r];
        g_h[0][i] = h;
        g_h[1][i] = h;
    }
}

__global__ void __launch_bounds__(NTHREADS, 1)
lstm_kernel(const float* __restrict__ x, const float* __restrict__ W,
            const float* __restrict__ bias, float* __restrict__ out) {
    __shared__ float a_sm[2][64][KC];        // 16 KB: A chunk [row][k]
    __shared__ float w_sm[2][KC][128];       // 32 KB: W chunk [k][gate*32+hc]

    const int tid = threadIdx.x;
    const int G   = gridDim.x;
    const int mg  = tid >> 5;    // row-group (8 rows each)
    const int hc  = tid & 31;    // h-column within tile

    // A staging: this thread stages float4 q of rows s_r0 and s_r0+32
    const int s_q  = tid & 7;
    const int s_r0 = tid >> 3;

    for (int d = 0; d < NDIAG; d++) {
        const int l_lo = (d - (TT - 1) > 0) ? d - (TT - 1) : 0;
        const int l_hi = (d < LL - 1) ? d : LL - 1;
        const int n    = l_hi - l_lo + 1;
        const int CG   = (n <= 18) ? 1 : (n <= 36) ? 2 : 4;  // cells per M-tile
        const int ngroups = (n + CG - 1) / CG;
        const int ntiles  = ngroups << 3;        // 8 nh-tiles per cell-group
        const int rp = (d + 1) & 1;              // read parity (prev diagonal's writes)
        const int wp = d & 1;                    // write parity
        const float* __restrict__ hin = g_h[rp];

        for (int tile = blockIdx.x; tile < ntiles; tile += G) {
            const int group  = tile >> 3;
            const int nh0    = (tile & 7) << 5;
            const int l_base = l_lo + group * CG;

            // --- per-thread staging pointer setup ---
            const float* aptr_in[2];
            const float* aptr_h[2];
            bool aok[2];
            #pragma unroll
            for (int p = 0; p < 2; p++) {
                int r  = s_r0 + (p << 5);
                int ci = r >> 4;
                int bb = r & 15;
                bool ok = (ci < CG) && (l_base + ci <= l_hi);
                int l = l_base + ci; if (l > l_hi) l = l_hi;  // clamp for safe addr
                int t = d - l;
                const float* pin = (l == 0) ? (x + (bb * TT + t) * HH)
                                            : (hin + ((l - 1) * BB + bb) * HH);
                const float* ph  = hin + (l * BB + bb) * HH;
                aptr_in[p] = pin + (s_q << 2);
                aptr_h[p]  = ph  + (s_q << 2);
                aok[p] = ok;
            }
            int wkk[4], wsoff[4];
            const float* wptr[4];
            #pragma unroll
            for (int p = 0; p < 4; p++) {
                int idx = tid + (p << 8);
                int kk  = idx >> 5;
                int c4  = idx & 31;
                int seg = c4 >> 3;
                int off = (c4 & 7) << 2;
                wkk[p]   = kk;
                wsoff[p] = seg * 32 + off;
                wptr[p]  = W + (size_t)kk * ZDIM + seg * 256 + nh0 + off;
            }

            float acc[8][4];
            #pragma unroll
            for (int r = 0; r < 8; r++)
                #pragma unroll
                for (int g = 0; g < 4; g++) acc[r][g] = 0.0f;

            const bool mgActive = (mg < (CG << 1));

            __syncthreads();  // smem safe vs previous tile

            // --- preload chunk 0 into buffer 0 ---
            float4 av[2]; float4 wv[4];
            #pragma unroll
            for (int p = 0; p < 2; p++)
                av[p] = aok[p] ? *reinterpret_cast<const float4*>(aptr_in[p])
                               : make_float4(0.f, 0.f, 0.f, 0.f);
            #pragma unroll
            for (int p = 0; p < 4; p++)
                wv[p] = *reinterpret_cast<const float4*>(wptr[p]);
            #pragma unroll
            for (int p = 0; p < 2; p++)
                if (aok[p]) *reinterpret_cast<float4*>(&a_sm[0][s_r0 + (p << 5)][s_q << 2]) = av[p];
            #pragma unroll
            for (int p = 0; p < 4; p++)
                *reinterpret_cast<float4*>(&w_sm[0][wkk[p]][wsoff[p]]) = wv[p];

            // --- K mainloop: 16 chunks, double-buffered ---
            #pragma unroll 1
            for (int chunk = 0; chunk < NCHUNK; chunk++) {
                const int cur = chunk & 1;
                __syncthreads();
                // prefetch chunk+1 to registers
                if (chunk + 1 < NCHUNK) {
                    int nc_  = chunk + 1;
                    int half = nc_ >> 3;            // 0: input cols, 1: h cols
                    int kof  = (nc_ & 7) * KC;
                    #pragma unroll
                    for (int p = 0; p < 2; p++) {
                        const float* bp = half ? aptr_h[p] : aptr_in[p];
                        av[p] = aok[p] ? *reinterpret_cast<const float4*>(bp + kof)
                                       : make_float4(0.f, 0.f, 0.f, 0.f);
                    }
                    size_t wrow = (size_t)(nc_ * KC) * ZDIM;
                    #pragma unroll
                    for (int p = 0; p < 4; p++)
                        wv[p] = *reinterpret_cast<const float4*>(wptr[p] + wrow);
                }
                // compute on current buffer
                if (mgActive) {
                    #pragma unroll
                    for (int kk4 = 0; kk4 < KC / 4; kk4++) {
                        float af[8][4];
                        #pragma unroll
                        for (int r = 0; r < 8; r++)
                            *reinterpret_cast<float4*>(af[r]) =
                                *reinterpret_cast<const float4*>(&a_sm[cur][(mg << 3) + r][kk4 << 2]);
                        #pragma unroll
                        for (int e = 0; e < 4; e++) {
                            int kk = (kk4 << 2) + e;
                            float w0 = w_sm[cur][kk][hc];
                            float w1 = w_sm[cur][kk][32 + hc];
                            float w2 = w_sm[cur][kk][64 + hc];
                            float w3 = w_sm[cur][kk][96 + hc];
                            #pragma unroll
                            for (int r = 0; r < 8; r++) {
                                float a = af[r][e];
                                acc[r][0] = fmaf(a, w0, acc[r][0]);
                                acc[r][1] = fmaf(a, w1, acc[r][1]);
                                acc[r][2] = fmaf(a, w2, acc[r][2]);
                                acc[r][3] = fmaf(a, w3, acc[r][3]);
                            }
                        }
                    }
                }
                // store prefetched chunk into the other buffer
                if (chunk + 1 < NCHUNK) {
                    int nb = cur ^ 1;
                    #pragma unroll
                    for (int p = 0; p < 2; p++)
                        if (aok[p]) *reinterpret_cast<float4*>(&a_sm[nb][s_r0 + (p << 5)][s_q << 2]) = av[p];
                    #pragma unroll
                    for (int p = 0; p < 4; p++)
                        *reinterpret_cast<float4*>(&w_sm[nb][wkk[p]][wsoff[p]]) = wv[p];
                }
            }

            // --- epilogue: gates + state update ---
            if (mgActive) {
                const int ci = mg >> 1;
                const int l  = l_base + ci;
                if (l <= l_hi) {
                    const int t    = d - l;
                    const int b0   = (mg & 1) << 3;
                    const int hcol = nh0 + hc;
                    const float bi = bias[hcol];
                    const float bj = bias[256 + hcol];
                    const float bf = bias[512 + hcol];
                    const float bo = bias[768 + hcol];
                    #pragma unroll
                    for (int j = 0; j < 8; j++) {
                        int bb   = b0 + j;
                        int sidx = (l * BB + bb) * HH + hcol;
                        float zi = acc[j][0] + bi;
                        float zj = acc[j][1] + bj;
                        float zf = acc[j][2] + bf;
                        float zo = acc[j][3] + bo;
                        float cold = g_c[sidx];
                        float ncv  = sig_(zf + 1.0f) * cold + sig_(zi) * tanh_(zj);
                        float nhv  = sig_(zo) * tanh_(ncv);
                        g_c[sidx]      = ncv;
                        g_h[wp][sidx]  = nhv;
                        if (l == LL - 1) out[(bb * TT + t) * HH + hcol] = nhv;
                    }
                }
            }
        } // tile loop

        // --- grid-wide barrier (release + L1 invalidate via membar.gpu) ---
        __threadfence();
        __syncthreads();
        if (tid == 0) {
            unsigned target = (unsigned)G * (unsigned)(d + 1);
            atomicAdd(&g_bar, 1u);
            while (*((volatile unsigned*)&g_bar) < target) { }
        }
        __syncthreads();
    }
}

extern "C" void kernel_launch(void* const* d_in, const int* in_sizes, int n_in,
                              void* d_out, int out_size) {
    const float* x    = (const float*)d_in[0];   // (B, T, H)
    const float* init = (const float*)d_in[1];   // (L, 2, B, H)
    const float* W    = (const float*)d_in[2];   // (2H, 4H)
    const float* bias = (const float*)d_in[3];   // (4H,)
    float* out        = (float*)d_out;           // (B, T, H)

    init_kernel<<<(LL * BB * HH + 255) / 256, 256>>>(init);
    lstm_kernel<<<GRID, NTHREADS>>>(x, W, bias, out);
}

// round 4
// speedup vs baseline: 1.5109x; 1.5109x over previous
#include <cuda_runtime.h>

#define TT 64
#define LL 64
#define BB 16
#define HH 256
#define KDIM 512      // 2H
#define ZDIM 1024     // 4H
#define NDIAG (TT + LL - 1)
#define GRID 148
#define NTHREADS 512
#define KC 32
#define NCHUNK (KDIM / KC)   // 16

// Persistent state (device globals: allocation-free scratch)
__device__ float g_c[LL * BB * HH];          // 4 MB
__device__ float g_h[2][LL * BB * HH];       // 8 MB (double-buffered by diagonal parity)
__device__ unsigned g_bar;

__device__ __forceinline__ float sig_(float v)  { return 1.0f / (1.0f + __expf(-v)); }
__device__ __forceinline__ float tanh_(float v) { return 2.0f / (1.0f + __expf(-2.0f * v)) - 1.0f; }

__global__ void init_kernel(const float* __restrict__ init_state) {
    int i = blockIdx.x * blockDim.x + threadIdx.x;
    if (i == 0) g_bar = 0u;
    if (i < LL * BB * HH) {
        int l = i / (BB * HH);
        int r = i - l * (BB * HH);
        g_c[i]    = init_state[(l * 2 + 0) * (BB * HH) + r];
        float h   = init_state[(l * 2 + 1) * (BB * HH) + r];
        g_h[0][i] = h;
        g_h[1][i] = h;
    }
}

// One K-chunk of the tile GEMM. Warp-uniform: warp w handles rows
// [RW*w, RW*w+RW), lane handles h-column hc (4 gates vectorized from w_sm).
template<int RW>
__device__ __forceinline__ void compute_chunk(
    const float (* __restrict__ a)[KC],        // [64][KC]
    const float (* __restrict__ wsm)[128],     // [KC][128]  col = hc*4 + gate
    int r0, int hc, float (&acc)[4][4])
{
    #pragma unroll
    for (int kk4 = 0; kk4 < KC / 4; kk4++) {
        float af[RW][4];
        #pragma unroll
        for (int j = 0; j < RW; j++)
            *reinterpret_cast<float4*>(af[j]) =
                *reinterpret_cast<const float4*>(&a[r0 + j][kk4 << 2]);
        #pragma unroll
        for (int e = 0; e < 4; e++) {
            float4 wf = *reinterpret_cast<const float4*>(&wsm[(kk4 << 2) + e][hc << 2]);
            #pragma unroll
            for (int j = 0; j < RW; j++) {
                float av = af[j][e];
                acc[j][0] = fmaf(av, wf.x, acc[j][0]);
                acc[j][1] = fmaf(av, wf.y, acc[j][1]);
                acc[j][2] = fmaf(av, wf.z, acc[j][2]);
                acc[j][3] = fmaf(av, wf.w, acc[j][3]);
            }
        }
    }
}

__global__ void __launch_bounds__(NTHREADS, 1)
lstm_kernel(const float* __restrict__ x, const float* __restrict__ W,
            const float* __restrict__ bias, float* __restrict__ out) {
    __shared__ float a_sm[2][64][KC];        // 16 KB: A chunk [row][k]
    __shared__ float w_sm[2][KC][128];       // 32 KB: W chunk [k][hc*4+gate]

    const int tid = threadIdx.x;
    const int G   = gridDim.x;
    const int w   = tid >> 5;    // warp 0..15
    const int hc  = tid & 31;    // h-column within 32-col tile (also W stage col)

    // A staging: thread stages float4 #s_q of row s_row (64 rows x 8 float4)
    const int s_q   = tid & 7;
    const int s_row = tid >> 3;

    for (int d = 0; d < NDIAG; d++) {
        const int l_lo = (d - (TT - 1) > 0) ? d - (TT - 1) : 0;
        const int l_hi = (d < LL - 1) ? d : LL - 1;
        const int n    = l_hi - l_lo + 1;
        const int CG   = (n + 17) / 18;          // 1..4 cells per M-tile; rows/warp = CG
        const int ngroups = (n + CG - 1) / CG;
        const int ntiles  = ngroups << 3;        // 8 nh-tiles per cell-group
        const int rp = (d + 1) & 1;              // read parity
        const int wp = d & 1;                    // write parity
        const float* __restrict__ hin = g_h[rp];

        for (int tile = blockIdx.x; tile < ntiles; tile += G) {
            const int group  = tile >> 3;
            const int nh0    = (tile & 7) << 5;
            const int l_base = l_lo + group * CG;

            // --- A staging pointers (1 row per thread) ---
            const int ci_s = s_row >> 4;
            const int bb_s = s_row & 15;
            const bool aok = (ci_s < CG) && (l_base + ci_s <= l_hi);
            int ls = l_base + ci_s; if (ls > l_hi) ls = l_hi;   // clamp for safe addr
            const int ts = d - ls;
            const float* pin = (ls == 0) ? (x + (bb_s * TT + ts) * HH)
                                         : (hin + ((ls - 1) * BB + bb_s) * HH);
            const float* ph  = hin + (ls * BB + bb_s) * HH;
            pin += s_q << 2;
            ph  += s_q << 2;

            // --- W staging base pointers: thread stages k-rows {w, 16+w}, col nh0+hc,
            //     4 gates strided 256 in global, packed as float4 in smem ---
            const float* wb0 = W + (size_t)w        * ZDIM + nh0 + hc;
            const float* wb1 = W + (size_t)(16 + w) * ZDIM + nh0 + hc;

            float acc[4][4];
            #pragma unroll
            for (int j = 0; j < 4; j++)
                #pragma unroll
                for (int g = 0; g < 4; g++) acc[j][g] = 0.0f;

            __syncthreads();  // smem safe vs previous tile

            // --- preload chunk 0 into buffer 0 ---
            float4 av = make_float4(0.f, 0.f, 0.f, 0.f);
            float wv0[4], wv1[4];
            if (aok) av = *reinterpret_cast<const float4*>(pin);
            #pragma unroll
            for (int g = 0; g < 4; g++) { wv0[g] = wb0[g * 256]; wv1[g] = wb1[g * 256]; }
            if (aok) *reinterpret_cast<float4*>(&a_sm[0][s_row][s_q << 2]) = av;
            *reinterpret_cast<float4*>(&w_sm[0][w][hc << 2])      = make_float4(wv0[0], wv0[1], wv0[2], wv0[3]);
            *reinterpret_cast<float4*>(&w_sm[0][16 + w][hc << 2]) = make_float4(wv1[0], wv1[1], wv1[2], wv1[3]);

            // --- K mainloop: 16 chunks, double-buffered ---
            #pragma unroll 1
            for (int chunk = 0; chunk < NCHUNK; chunk++) {
                const int cur = chunk & 1;
                __syncthreads();
                // prefetch chunk+1 into registers
                if (chunk + 1 < NCHUNK) {
                    const int nc_ = chunk + 1;
                    const int kof = (nc_ & 7) * KC;
                    const float* bp = (nc_ >= 8) ? ph : pin;
                    av = aok ? *reinterpret_cast<const float4*>(bp + kof)
                             : make_float4(0.f, 0.f, 0.f, 0.f);
                    const size_t wrow = (size_t)nc_ * KC * ZDIM;
                    #pragma unroll
                    for (int g = 0; g < 4; g++) {
                        wv0[g] = wb0[wrow + g * 256];
                        wv1[g] = wb1[wrow + g * 256];
                    }
                }
                // compute on current buffer (all 16 warps active, rows/warp = CG)
                if      (CG == 4) compute_chunk<4>(a_sm[cur], w_sm[cur], w << 2, hc, acc);
                else if (CG == 3) compute_chunk<3>(a_sm[cur], w_sm[cur], w * 3,  hc, acc);
                else if (CG == 2) compute_chunk<2>(a_sm[cur], w_sm[cur], w << 1, hc, acc);
                else              compute_chunk<1>(a_sm[cur], w_sm[cur], w,      hc, acc);
                // store prefetched chunk into the other buffer
                if (chunk + 1 < NCHUNK) {
                    const int nb = cur ^ 1;
                    if (aok) *reinterpret_cast<float4*>(&a_sm[nb][s_row][s_q << 2]) = av;
                    *reinterpret_cast<float4*>(&w_sm[nb][w][hc << 2])      = make_float4(wv0[0], wv0[1], wv0[2], wv0[3]);
                    *reinterpret_cast<float4*>(&w_sm[nb][16 + w][hc << 2]) = make_float4(wv1[0], wv1[1], wv1[2], wv1[3]);
                }
            }

            // --- epilogue: gates + state update (rows CG*w + j, j < CG) ---
            {
                const int hcol = nh0 + hc;
                const float bi = bias[hcol];
                const float bj = bias[256 + hcol];
                const float bf = bias[512 + hcol];
                const float bo = bias[768 + hcol];
                const int rowbase = w * CG;
                #pragma unroll
                for (int j = 0; j < 4; j++) {
                    if (j < CG) {
                        const int row = rowbase + j;
                        const int ci  = row >> 4;
                        const int bb  = row & 15;
                        const int l   = l_base + ci;
                        if (l <= l_hi) {
                            const int t    = d - l;
                            const int sidx = (l * BB + bb) * HH + hcol;
                            float zi = acc[j][0] + bi;
                            float zj = acc[j][1] + bj;
                            float zf = acc[j][2] + bf;
                            float zo = acc[j][3] + bo;
                            float cold = g_c[sidx];
                            float ncv  = sig_(zf + 1.0f) * cold + sig_(zi) * tanh_(zj);
                            float nhv  = sig_(zo) * tanh_(ncv);
                            g_c[sidx]     = ncv;
                            g_h[wp][sidx] = nhv;
                            if (l == LL - 1) out[(bb * TT + t) * HH + hcol] = nhv;
                        }
                    }
                }
            }
        } // tile loop

        // --- grid-wide barrier (release + L1 invalidate via membar.gpu) ---
        __threadfence();
        __syncthreads();
        if (tid == 0) {
            unsigned target = (unsigned)G * (unsigned)(d + 1);
            atomicAdd(&g_bar, 1u);
            while (*((volatile unsigned*)&g_bar) < target) { }
        }
        __syncthreads();
    }
}

extern "C" void kernel_launch(void* const* d_in, const int* in_sizes, int n_in,
                              void* d_out, int out_size) {
    const float* x    = (const float*)d_in[0];   // (B, T, H)
    const float* init = (const float*)d_in[1];   // (L, 2, B, H)
    const float* W    = (const float*)d_in[2];   // (2H, 4H)
    const float* bias = (const float*)d_in[3];   // (4H,)
    float* out        = (float*)d_out;           // (B, T, H)

    init_kernel<<<(LL * BB * HH + 255) / 256, 256>>>(init);
    lstm_kernel<<<GRID, NTHREADS>>>(x, W, bias, out);
}

// round 5
// speedup vs baseline: 1.6381x; 1.0842x over previous
#include <cuda_runtime.h>

#define TT 64
#define LL 64
#define BB 16
#define HH 256
#define KDIM 512      // 2H
#define ZDIM 1024     // 4H
#define NDIAG (TT + LL - 1)
#define GRID 148
#define NTHREADS 512
#define KC 32
#define NCHUNK (KDIM / KC)   // 16

typedef unsigned long long u64;

// Persistent state (device globals: allocation-free scratch)
__device__ float g_c[LL * BB * HH];          // 4 MB
__device__ float g_h[2][LL * BB * HH];       // 8 MB (double-buffered by diagonal parity)
__device__ unsigned g_bar;

__device__ __forceinline__ float sig_(float v)  { return 1.0f / (1.0f + __expf(-v)); }
__device__ __forceinline__ float tanh_(float v) { return 2.0f / (1.0f + __expf(-2.0f * v)) - 1.0f; }

// Packed fp32x2 FMA (SASS FFMA2): d.lo += a.lo*b.lo ; d.hi += a.hi*b.hi
__device__ __forceinline__ void ffma2(u64 &d, u64 a, u64 b) {
    asm("fma.rn.f32x2 %0, %1, %2, %0;" : "+l"(d) : "l"(a), "l"(b));
}
__device__ __forceinline__ float fold2(u64 p) {
    float2 f;
    f = *reinterpret_cast<float2*>(&p);
    return f.x + f.y;
}

__global__ void init_kernel(const float* __restrict__ init_state) {
    int i = blockIdx.x * blockDim.x + threadIdx.x;
    if (i == 0) g_bar = 0u;
    if (i < LL * BB * HH) {
        int l = i / (BB * HH);
        int r = i - l * (BB * HH);
        g_c[i]    = init_state[(l * 2 + 0) * (BB * HH) + r];
        float h   = init_state[(l * 2 + 1) * (BB * HH) + r];
        g_h[0][i] = h;
        g_h[1][i] = h;
    }
}

// Per-tile body. Warps 0-7: rows (w*RW..), k 0..15 of each chunk.
// Warps 8-15: same rows, k 16..31. Partials combined via smem at the end.
template<int CG>
__device__ __forceinline__ void tile_body(
    float (*a_sm)[64][KC], float2 (*w2_sm)[16][128], float* xch,
    const float* __restrict__ x, const float* __restrict__ W,
    const float* __restrict__ bias, float* __restrict__ out,
    const float* __restrict__ hin, float* __restrict__ hout,
    int d, int l_lo, int l_hi, int tile)
{
    constexpr int RW = 2 * CG;
    const int tid = threadIdx.x;
    const int w   = tid >> 5;
    const int hc  = tid & 31;
    const int group  = tile >> 3;
    const int nh0    = (tile & 7) << 5;
    const int l_base = l_lo + group * CG;

    // --- A staging: thread stages float4 #s_q of row s_row ---
    const int s_q   = tid & 7;
    const int s_row = tid >> 3;
    const int ci_s  = s_row >> 4;
    const int bb_s  = s_row & 15;
    const bool aok  = (ci_s < CG) && (l_base + ci_s <= l_hi);
    int ls = l_base + ci_s; if (ls > l_hi) ls = l_hi;   // clamp for safe addr
    const int ts = d - ls;
    const float* pin = (ls == 0) ? (x + (bb_s * TT + ts) * HH)
                                 : (hin + ((ls - 1) * BB + bb_s) * HH);
    const float* ph  = hin + (ls * BB + bb_s) * HH;
    pin += s_q << 2;
    ph  += s_q << 2;

    // --- W staging: thread owns k-pair wk2 (k = 2*wk2, 2*wk2+1), col hc, 4 gates ---
    const int wk2 = tid >> 5;        // 0..15
    const float* wbase = W + nh0 + hc;

    u64 acc[RW][4];
    #pragma unroll
    for (int j = 0; j < RW; j++)
        #pragma unroll
        for (int g = 0; g < 4; g++) acc[j][g] = 0ull;

    const int r0     = (w & 7) * RW;
    const int k2base = (w >> 3) << 3;   // 0 or 8

    __syncthreads();  // smem safe vs previous tile's reads

    // --- preload chunk 0 into buffer 0 ---
    float4 av = make_float4(0.f, 0.f, 0.f, 0.f);
    float wlo[4], whi[4];
    if (aok) av = *reinterpret_cast<const float4*>(pin);
    {
        const size_t kg = (size_t)(wk2 << 1);
        #pragma unroll
        for (int g = 0; g < 4; g++) {
            wlo[g] = wbase[kg * ZDIM + g * 256];
            whi[g] = wbase[(kg + 1) * ZDIM + g * 256];
        }
    }
    if (aok) *reinterpret_cast<float4*>(&a_sm[0][s_row][s_q << 2]) = av;
    #pragma unroll
    for (int g = 0; g < 4; g++)
        w2_sm[0][wk2][g * 32 + hc] = make_float2(wlo[g], whi[g]);

    // --- K mainloop: 16 chunks, double-buffered ---
    #pragma unroll 1
    for (int chunk = 0; chunk < NCHUNK; chunk++) {
        const int cur = chunk & 1;
        __syncthreads();
        // prefetch chunk+1 into registers
        if (chunk + 1 < NCHUNK) {
            const int nc  = chunk + 1;
            const int kof = (nc & 7) * KC;
            const float* bp = (nc >= 8) ? ph : pin;
            av = aok ? *reinterpret_cast<const float4*>(bp + kof)
                     : make_float4(0.f, 0.f, 0.f, 0.f);
            const size_t kg = (size_t)nc * KC + (wk2 << 1);
            #pragma unroll
            for (int g = 0; g < 4; g++) {
                wlo[g] = wbase[kg * ZDIM + g * 256];
                whi[g] = wbase[(kg + 1) * ZDIM + g * 256];
            }
        }
        // compute on current buffer (this warp's k-half, RW rows)
        {
            const float  (*a)[KC]   = a_sm[cur];
            const float2 (*w2)[128] = w2_sm[cur];
            #pragma unroll
            for (int q = 0; q < 8; q++) {
                const int k2 = k2base + q;
                u64 ap[RW];
                #pragma unroll
                for (int j = 0; j < RW; j++)
                    ap[j] = *reinterpret_cast<const u64*>(&a[r0 + j][k2 << 1]);
                #pragma unroll
                for (int g = 0; g < 4; g++) {
                    u64 wp = *reinterpret_cast<const u64*>(&w2[k2][g * 32 + hc]);
                    #pragma unroll
                    for (int j = 0; j < RW; j++)
                        ffma2(acc[j][g], ap[j], wp);
                }
            }
        }
        // store prefetched chunk into the other buffer
        if (chunk + 1 < NCHUNK) {
            const int nb = cur ^ 1;
            if (aok) *reinterpret_cast<float4*>(&a_sm[nb][s_row][s_q << 2]) = av;
            #pragma unroll
            for (int g = 0; g < 4; g++)
                w2_sm[nb][wk2][g * 32 + hc] = make_float2(wlo[g], whi[g]);
        }
    }

    // --- combine k-halves: warps 8-15 export partials, warps 0-7 finish ---
    __syncthreads();   // all compute reads of smem done; safe to overlay xch
    if (w >= 8) {
        #pragma unroll
        for (int j = 0; j < RW; j++)
            #pragma unroll
            for (int g = 0; g < 4; g++)
                xch[(((w - 8) << 3) + j) * 128 + g * 32 + hc] = fold2(acc[j][g]);
    }
    __syncthreads();
    if (w < 8) {
        const int hcol = nh0 + hc;
        const float bi = bias[hcol];
        const float bj = bias[256 + hcol];
        const float bf = bias[512 + hcol];
        const float bo = bias[768 + hcol];
        #pragma unroll
        for (int j = 0; j < RW; j++) {
            const int row = w * RW + j;
            const int ci  = row >> 4;
            const int bb  = row & 15;
            const int l   = l_base + ci;
            if (l <= l_hi) {
                const int t    = d - l;
                const int sidx = (l * BB + bb) * HH + hcol;
                const float* xr = &xch[((w << 3) + j) * 128 + hc];
                float zi = fold2(acc[j][0]) + xr[0]  + bi;
                float zj = fold2(acc[j][1]) + xr[32] + bj;
                float zf = fold2(acc[j][2]) + xr[64] + bf;
                float zo = fold2(acc[j][3]) + xr[96] + bo;
                float cold = g_c[sidx];
                float ncv  = sig_(zf + 1.0f) * cold + sig_(zi) * tanh_(zj);
                float nhv  = sig_(zo) * tanh_(ncv);
                g_c[sidx] = ncv;
                hout[sidx] = nhv;
                if (l == LL - 1) out[(bb * TT + t) * HH + hcol] = nhv;
            }
        }
    }
}

__global__ void __launch_bounds__(NTHREADS, 1)
lstm_kernel(const float* __restrict__ x, const float* __restrict__ W,
            const float* __restrict__ bias, float* __restrict__ out) {
    // 48 KB static smem, three overlapping views:
    //   a_sm : float [2][64][32]      @0      (16 KB)  A chunk [row][k]
    //   w2_sm: float2[2][16][128]     @16384  (32 KB)  W k-pairs [k/2][gate*32+hc]
    //   xch  : float [8][8][4][32]    @16384  (32 KB)  k-half partial exchange (post-mainloop)
    __shared__ __align__(16) char smem_raw[49152];
    float  (*a_sm)[64][KC]   = reinterpret_cast<float (*)[64][KC]>(smem_raw);
    float2 (*w2_sm)[16][128] = reinterpret_cast<float2 (*)[16][128]>(smem_raw + 16384);
    float*  xch              = reinterpret_cast<float*>(smem_raw + 16384);

    const int tid = threadIdx.x;
    const int G   = gridDim.x;

    for (int d = 0; d < NDIAG; d++) {
        const int l_lo = (d - (TT - 1) > 0) ? d - (TT - 1) : 0;
        const int l_hi = (d < LL - 1) ? d : LL - 1;
        const int n    = l_hi - l_lo + 1;
        const int CG   = (n + 17) / 18;          // 1..4 cells per M-tile
        const int ngroups = (n + CG - 1) / CG;
        const int ntiles  = ngroups << 3;        // 8 nh-tiles per cell-group (<=144)
        const int rp = (d + 1) & 1;              // read parity
        const int wp = d & 1;                    // write parity
        const float* hin  = g_h[rp];
        float*       hout = g_h[wp];

        for (int tile = blockIdx.x; tile < ntiles; tile += G) {
            if      (CG == 4) tile_body<4>(a_sm, w2_sm, xch, x, W, bias, out, hin, hout, d, l_lo, l_hi, tile);
            else if (CG == 3) tile_body<3>(a_sm, w2_sm, xch, x, W, bias, out, hin, hout, d, l_lo, l_hi, tile);
            else if (CG == 2) tile_body<2>(a_sm, w2_sm, xch, x, W, bias, out, hin, hout, d, l_lo, l_hi, tile);
            else              tile_body<1>(a_sm, w2_sm, xch, x, W, bias, out, hin, hout, d, l_lo, l_hi, tile);
        }

        // --- grid-wide barrier (release + L1 invalidate via membar.gpu) ---
        if (d < NDIAG - 1) {
            __threadfence();
            __syncthreads();
            if (tid == 0) {
                unsigned target = (unsigned)G * (unsigned)(d + 1);
                atomicAdd(&g_bar, 1u);
                while (*((volatile unsigned*)&g_bar) < target) { }
            }
            __syncthreads();
        }
    }
}

extern "C" void kernel_launch(void* const* d_in, const int* in_sizes, int n_in,
                              void* d_out, int out_size) {
    const float* x    = (const float*)d_in[0];   // (B, T, H)
    const float* init = (const float*)d_in[1];   // (L, 2, B, H)
    const float* W    = (const float*)d_in[2];   // (2H, 4H)
    const float* bias = (const float*)d_in[3];   // (4H,)
    float* out        = (float*)d_out;           // (B, T, H)

    init_kernel<<<(LL * BB * HH + 255) / 256, 256>>>(init);
    lstm_kernel<<<GRID, NTHREADS>>>(x, W, bias, out);
}

// round 7
// speedup vs baseline: 1.7403x; 1.0624x over previous
#include <cuda_runtime.h>
#include <cstdint>

#define TT 64
#define LL 64
#define BB 16
#define HH 256
#define ZDIM 1024     // 4H
#define NDIAG 127
#define GRID 148
#define NTHREADS 512
#define KC 32
#define NCHUNK 16
// dynamic smem: W stages [4][16KB] @0 ; A stages [4][8KB] @65536
#define SMEM_A_OFF 65536
#define SMEM_TOTAL 98304

typedef unsigned long long u64;

// Persistent state (device globals: allocation-free scratch)
__device__ float g_c[LL * BB * HH];             // 4 MB
__device__ float g_h[2][LL * BB * HH];          // 8 MB (double-buffered by parity)
__device__ float g_Wpack[8 * 16 * 16 * 128 * 2]; // 2 MB  [nh][chunk][k2][g*32+hc] float2
__device__ unsigned g_bar;

__device__ __forceinline__ float sig_(float v)  { return 1.0f / (1.0f + __expf(-v)); }
__device__ __forceinline__ float tanh_(float v) { return 2.0f / (1.0f + __expf(-2.0f * v)) - 1.0f; }

// Packed fp32x2 FMA (SASS FFMA2): d.lo += a.lo*b.lo ; d.hi += a.hi*b.hi
__device__ __forceinline__ void ffma2(u64 &d, u64 a, u64 b) {
    asm("fma.rn.f32x2 %0, %1, %2, %0;" : "+l"(d) : "l"(a), "l"(b));
}
__device__ __forceinline__ float fold2(u64 p) {
    float2 f = *reinterpret_cast<float2*>(&p);
    return f.x + f.y;
}
__device__ __forceinline__ void cpa16(uint32_t d, const void* s) {
    asm volatile("cp.async.cg.shared.global [%0], [%1], 16;" :: "r"(d), "l"(s));
}
__device__ __forceinline__ void cpcommit() { asm volatile("cp.async.commit_group;"); }
template<int N> __device__ __forceinline__ void cpwait() {
    asm volatile("cp.async.wait_group %0;" :: "n"(N));
}

__global__ void init_kernel(const float* __restrict__ init_state) {
    int i = blockIdx.x * blockDim.x + threadIdx.x;
    if (i == 0) g_bar = 0u;
    if (i < LL * BB * HH) {
        int l = i / (BB * HH);
        int r = i - l * (BB * HH);
        g_c[i]    = init_state[(l * 2 + 0) * (BB * HH) + r];
        float h   = init_state[(l * 2 + 1) * (BB * HH) + r];
        g_h[0][i] = h;
        g_h[1][i] = h;
    }
}

// Pre-swizzle W into the per-tile smem layout so W stage fills are straight copies.
__global__ void prep_kernel(const float* __restrict__ W) {
    int idx = blockIdx.x * blockDim.x + threadIdx.x;   // float2 index
    if (idx >= 8 * 16 * 16 * 128) return;
    int col = idx & 127;          // g*32 + hc
    int k2  = (idx >> 7) & 15;
    int c   = (idx >> 11) & 15;
    int b   = idx >> 15;          // nh block
    int k   = c * KC + (k2 << 1);
    int gcol = (col >> 5) * 256 + b * 32 + (col & 31);
    g_Wpack[idx * 2]     = W[(size_t)k * ZDIM + gcol];
    g_Wpack[idx * 2 + 1] = W[(size_t)(k + 1) * ZDIM + gcol];
}

// Per-tile body. Warps 0-7: k 0..15 of each chunk; warps 8-15: k 16..31.
// Partials combined via smem exchange (overlaid on stage buffers) at tile end.
template<int CG>
__device__ __forceinline__ void tile_body(
    char* smem, const float* __restrict__ x,
    const float* __restrict__ bias, float* __restrict__ out,
    const float* __restrict__ hin, float* __restrict__ hout,
    int d, int l_lo, int l_hi, int tile)
{
    constexpr int RW = 2 * CG;
    const int tid = threadIdx.x;
    const int w   = tid >> 5;
    const int hc  = tid & 31;
    const int group  = tile >> 3;
    const int nh0    = (tile & 7) << 5;
    const int l_base = l_lo + group * CG;

    // --- A source pointers (1 row per thread, clamped so always valid) ---
    const int s_q   = tid & 7;
    const int s_row = tid >> 3;
    const int ci_s  = s_row >> 4;
    const int bb_s  = s_row & 15;
    int ls = l_base + ci_s; if (ls > l_hi) ls = l_hi;
    const int ts = d - ls;
    const float* pin = (ls == 0) ? (x + (bb_s * TT + ts) * HH)
                                 : (hin + ((ls - 1) * BB + bb_s) * HH);
    const float* ph  = hin + (ls * BB + bb_s) * HH;
    pin += s_q << 2;
    ph  += s_q << 2;

    const float* wblk = g_Wpack + (size_t)(tile & 7) * 16 * 4096;  // per-nh block (floats)

    const uint32_t sbase  = (uint32_t)__cvta_generic_to_shared(smem);
    const uint32_t a_dst0 = sbase + SMEM_A_OFF + (((s_row << 5) + (s_q << 2)) << 2);
    const uint32_t w_dst0 = sbase + tid * 32;

    u64 acc[RW][4];
    #pragma unroll
    for (int j = 0; j < RW; j++)
        #pragma unroll
        for (int g = 0; g < 4; g++) acc[j][g] = 0ull;

    const int r0     = (w & 7) * RW;
    const int k2base = (w >> 3) << 3;   // 0 or 8

    __syncthreads();   // close out previous tile's smem use

    // --- issue chunks 0..2 (one group each) ---
    #pragma unroll
    for (int c = 0; c < 3; c++) {
        const float* asrc = ((c & 8) ? ph : pin) + (c & 7) * KC;
        cpa16(a_dst0 + c * 8192, asrc);
        const float* wsrc = wblk + (size_t)c * 4096 + tid * 8;
        cpa16(w_dst0 + c * 16384, wsrc);
        cpa16(w_dst0 + c * 16384 + 16, wsrc + 4);
        cpcommit();
    }

    // --- K mainloop: 16 chunks, 4-stage cp.async ring, issue depth 3 ---
    #pragma unroll 1
    for (int c = 0; c < NCHUNK; c++) {
        cpwait<2>();         // chunk c's group complete (uniform: empty groups at tail)
        __syncthreads();
        if (c + 3 < NCHUNK) {
            const int nc = c + 3, s = nc & 3;
            const float* asrc = ((nc & 8) ? ph : pin) + (nc & 7) * KC;
            cpa16(a_dst0 + s * 8192, asrc);
            const float* wsrc = wblk + (size_t)nc * 4096 + tid * 8;
            cpa16(w_dst0 + s * 16384, wsrc);
            cpa16(w_dst0 + s * 16384 + 16, wsrc + 4);
            cpcommit();
        } else {
            cpcommit();      // empty group keeps wait_group accounting uniform
        }
        const int s = c & 3;
        const float*  a  = (const float*)(smem + SMEM_A_OFF + s * 8192);   // [64][32]
        const float2* w2 = (const float2*)(smem + s * 16384);              // [16][128]
        #pragma unroll
        for (int q = 0; q < 8; q++) {
            const int k2 = k2base + q;
            u64 ap[RW];
            #pragma unroll
            for (int j = 0; j < RW; j++)
                ap[j] = *reinterpret_cast<const u64*>(a + (r0 + j) * KC + (k2 << 1));
            #pragma unroll
            for (int g = 0; g < 4; g++) {
                u64 wp = *reinterpret_cast<const u64*>(w2 + k2 * 128 + g * 32 + hc);
                #pragma unroll
                for (int j = 0; j < RW; j++)
                    ffma2(acc[j][g], ap[j], wp);
            }
        }
    }

    // --- combine k-halves: warps 8-15 export partials, warps 0-7 finish ---
    __syncthreads();
    float* xch = (float*)smem;   // overlays W stages 0-1 (32 KB), all compute done
    if (w >= 8) {
        #pragma unroll
        for (int j = 0; j < RW; j++)
            #pragma unroll
            for (int g = 0; g < 4; g++)
                xch[(((w - 8) * RW) + j) * 128 + g * 32 + hc] = fold2(acc[j][g]);
    }
    __syncthreads();
    if (w < 8) {
        const int hcol = nh0 + hc;
        const float bi = bias[hcol];
        const float bj = bias[256 + hcol];
        const float bf = bias[512 + hcol];
        const float bo = bias[768 + hcol];
        #pragma unroll
        for (int j = 0; j < RW; j++) {
            const int row = w * RW + j;
            const int ci  = row >> 4;
            const int bb  = row & 15;
            const int l   = l_base + ci;
            if (l <= l_hi) {
                const int t    = d - l;
                const int sidx = (l * BB + bb) * HH + hcol;
                const float* xr = &xch[(w * RW + j) * 128 + hc];
                float zi = fold2(acc[j][0]) + xr[0]  + bi;
                float zj = fold2(acc[j][1]) + xr[32] + bj;
                float zf = fold2(acc[j][2]) + xr[64] + bf;
                float zo = fold2(acc[j][3]) + xr[96] + bo;
                float cold = g_c[sidx];
                float ncv  = sig_(zf + 1.0f) * cold + sig_(zi) * tanh_(zj);
                float nhv  = sig_(zo) * tanh_(ncv);
                g_c[sidx]  = ncv;
                hout[sidx] = nhv;
                if (l == LL - 1) out[(bb * TT + t) * HH + hcol] = nhv;
            }
        }
    }
}

__global__ void __launch_bounds__(NTHREADS, 1)
lstm_kernel(const float* __restrict__ x, const float* __restrict__ bias,
            float* __restrict__ out) {
    extern __shared__ __align__(16) char smem[];
    const int tid = threadIdx.x;
    const int G   = gridDim.x;

    for (int d = 0; d < NDIAG; d++) {
        const int l_lo = (d - (TT - 1) > 0) ? d - (TT - 1) : 0;
        const int l_hi = (d < LL - 1) ? d : LL - 1;
        const int n    = l_hi - l_lo + 1;
        const int CG   = (n + 17) / 18;          // 1..4 cells per M-tile
        const int ngroups = (n + CG - 1) / CG;
        const int ntiles  = ngroups << 3;        // 8 nh-tiles per cell-group (<=144)
        const int rp = (d + 1) & 1;
        const int wp = d & 1;
        const float* hin  = g_h[rp];
        float*       hout = g_h[wp];

        for (int tile = blockIdx.x; tile < ntiles; tile += G) {
            if      (CG == 4) tile_body<4>(smem, x, bias, out, hin, hout, d, l_lo, l_hi, tile);
            else if (CG == 3) tile_body<3>(smem, x, bias, out, hin, hout, d, l_lo, l_hi, tile);
            else if (CG == 2) tile_body<2>(smem, x, bias, out, hin, hout, d, l_lo, l_hi, tile);
            else              tile_body<1>(smem, x, bias, out, hin, hout, d, l_lo, l_hi, tile);
        }

        // --- grid-wide barrier (release + L1 invalidate via membar.gpu) ---
        if (d < NDIAG - 1) {
            __threadfence();
            __syncthreads();
            if (tid == 0) {
                unsigned target = (unsigned)G * (unsigned)(d + 1);
                atomicAdd(&g_bar, 1u);
                while (*((volatile unsigned*)&g_bar) < target) { }
            }
            __syncthreads();
        }
    }
}

extern "C" void kernel_launch(void* const* d_in, const int* in_sizes, int n_in,
                              void* d_out, int out_size) {
    const float* x    = (const float*)d_in[0];   // (B, T, H)
    const float* init = (const float*)d_in[1];   // (L, 2, B, H)
    const float* W    = (const float*)d_in[2];   // (2H, 4H)
    const float* bias = (const float*)d_in[3];   // (4H,)
    float* out        = (float*)d_out;           // (B, T, H)

    cudaFuncSetAttribute(lstm_kernel, cudaFuncAttributeMaxDynamicSharedMemorySize, SMEM_TOTAL);
    init_kernel<<<(LL * BB * HH + 255) / 256, 256>>>(init);
    prep_kernel<<<(8 * 16 * 16 * 128 + 255) / 256, 256>>>(W);
    lstm_kernel<<<GRID, NTHREADS, SMEM_TOTAL>>>(x, bias, out);
}

// round 9
// speedup vs baseline: 1.7731x; 1.0188x over previous
#include <cuda_runtime.h>
#include <cstdint>

#define TT 64
#define LL 64
#define BB 16
#define HH 256
#define ZDIM 1024     // 4H
#define NDIAG 127
#define GRID 148
#define NTHREADS 512
#define KC 64
#define NCHUNK 8
// 3 stages x 48KB: W[32][128]f2 @ +0 (32KB), A[64][64]f @ +32768 (16KB)
#define STAGE_BYTES 49152
#define A_OFF 32768
#define SMEM_TOTAL (3 * STAGE_BYTES)

typedef unsigned long long u64;

// Persistent state (device globals: allocation-free scratch)
__device__ float g_c[LL * BB * HH];              // 4 MB
__device__ float g_h[2][LL * BB * HH];           // 8 MB (double-buffered by parity)
__device__ float g_Wpack[8 * 8 * 32 * 128 * 2];  // 2 MB  [nh][chunk][k2][g*32+hc] float2
__device__ unsigned g_bar;

__device__ __forceinline__ float sig_(float v)  { return 1.0f / (1.0f + __expf(-v)); }
__device__ __forceinline__ float tanh_(float v) { return 2.0f / (1.0f + __expf(-2.0f * v)) - 1.0f; }

// Packed fp32x2 FMA (SASS FFMA2)
__device__ __forceinline__ void ffma2(u64 &d, u64 a, u64 b) {
    asm("fma.rn.f32x2 %0, %1, %2, %0;" : "+l"(d) : "l"(a), "l"(b));
}
__device__ __forceinline__ float fold2(u64 p) {
    float2 f = *reinterpret_cast<float2*>(&p);
    return f.x + f.y;
}
__device__ __forceinline__ void cpa16(uint32_t d, const void* s) {
    asm volatile("cp.async.cg.shared.global [%0], [%1], 16;" :: "r"(d), "l"(s));
}
__device__ __forceinline__ void cpcommit() { asm volatile("cp.async.commit_group;"); }
template<int N> __device__ __forceinline__ void cpwait() {
    asm volatile("cp.async.wait_group %0;" :: "n"(N));
}

__global__ void init_kernel(const float* __restrict__ init_state) {
    int i = blockIdx.x * blockDim.x + threadIdx.x;
    if (i == 0) g_bar = 0u;
    if (i < LL * BB * HH) {
        int l = i / (BB * HH);
        int r = i - l * (BB * HH);
        g_c[i]    = init_state[(l * 2 + 0) * (BB * HH) + r];
        float h   = init_state[(l * 2 + 1) * (BB * HH) + r];
        g_h[0][i] = h;
        g_h[1][i] = h;
    }
}

// Pre-swizzle W into per-tile smem layout: [nh][chunk(8)][k2(32)][g*32+hc] float2
__global__ void prep_kernel(const float* __restrict__ W) {
    int idx = blockIdx.x * blockDim.x + threadIdx.x;   // float2 index
    if (idx >= 8 * 8 * 32 * 128) return;
    int col = idx & 127;           // g*32 + hc
    int k2  = (idx >> 7) & 31;
    int c   = (idx >> 12) & 7;
    int b   = idx >> 15;           // nh block
    int k   = c * KC + (k2 << 1);
    int gcol = (col >> 5) * 256 + b * 32 + (col & 31);
    g_Wpack[idx * 2]     = W[(size_t)k * ZDIM + gcol];
    g_Wpack[idx * 2 + 1] = W[(size_t)(k + 1) * ZDIM + gcol];
}

// Stage one W chunk (32KB) into stage s: 64B per thread = 4 cp.async.
__device__ __forceinline__ void issueW(uint32_t sbase, int nh, int c, int s, int tid) {
    const float* wsrc = g_Wpack + ((size_t)(nh * 8 + c) << 13) + tid * 16;
    uint32_t dst = sbase + s * STAGE_BYTES + tid * 64;
    cpa16(dst, wsrc);
    cpa16(dst + 16, wsrc + 4);
    cpa16(dst + 32, wsrc + 8);
    cpa16(dst + 48, wsrc + 12);
}

// Per-tile body. Warps 0-7: k2 0..15 of each chunk; warps 8-15: k2 16..31.
template<int CG>
__device__ __forceinline__ void tile_body(
    char* smem, const float* __restrict__ x,
    const float* __restrict__ bias, float* __restrict__ out,
    const float* __restrict__ hin, float* __restrict__ hout,
    int d, int l_lo, int l_hi, int tile)
{
    constexpr int RW = 2 * CG;
    const int tid = threadIdx.x;
    const int w   = tid >> 5;
    const int hc  = tid & 31;
    const int nh      = tile & 7;
    const int nh0     = nh << 5;
    const int group   = tile >> 3;
    const int l_base  = l_lo + group * CG;

    // --- A source pointers (1 row per thread, clamped so always valid) ---
    const int s_row = tid >> 3;
    const int p8    = (tid & 7) << 3;     // float offset within row (8 floats/thread)
    const int ci_s  = s_row >> 4;
    const int bb_s  = s_row & 15;
    int ls = l_base + ci_s; if (ls > l_hi) ls = l_hi;
    const int ts = d - ls;
    const float* pin = ((ls == 0) ? (x + (bb_s * TT + ts) * HH)
                                  : (hin + ((ls - 1) * BB + bb_s) * HH)) + p8;
    const float* ph  = hin + (ls * BB + bb_s) * HH + p8;

    const uint32_t sbase = (uint32_t)__cvta_generic_to_shared(smem);
    const uint32_t a_dst = sbase + A_OFF + (s_row << 8) + ((tid & 7) << 5);

    // --- issue A chunks 0,1 into stages 0,1 (W0,W1 already in flight pre-barrier) ---
    cpa16(a_dst, pin);               cpa16(a_dst + 16, pin + 4);               cpcommit();
    cpa16(a_dst + STAGE_BYTES, pin + KC); cpa16(a_dst + STAGE_BYTES + 16, pin + KC + 4); cpcommit();

    u64 acc[RW][4];
    #pragma unroll
    for (int j = 0; j < RW; j++)
        #pragma unroll
        for (int g = 0; g < 4; g++) acc[j][g] = 0ull;

    const int r0     = (w & 7) * RW;
    const int k2base = (w >> 3) << 4;   // 0 or 16

    // --- K mainloop: 8 chunks, 3-stage ring, lookahead 2 ---
    #pragma unroll 1
    for (int c = 0; c < NCHUNK; c++) {
        cpwait<1>();
        __syncthreads();                 // chunk c visible; all warps done with c-1
        if (c + 2 < NCHUNK) {
            const int nc = c + 2;
            const int sn = (nc >= 6) ? nc - 6 : (nc >= 3 ? nc - 3 : nc);
            issueW(sbase, nh, nc, sn, tid);
            const float* asrc = ((nc & 4) ? ph : pin) + (nc & 3) * KC;
            uint32_t ad = a_dst + sn * STAGE_BYTES;
            cpa16(ad, asrc); cpa16(ad + 16, asrc + 4);
        }
        cpcommit();
        const int s = (c >= 6) ? c - 6 : (c >= 3 ? c - 3 : c);
        const float*  a  = (const float*)(smem + s * STAGE_BYTES + A_OFF) + r0 * KC;
        const float2* w2 = (const float2*)(smem + s * STAGE_BYTES) + hc;
        #pragma unroll
        for (int q = 0; q < 16; q++) {
            const int k2 = k2base + q;
            u64 ap[RW];
            #pragma unroll
            for (int j = 0; j < RW; j++)
                ap[j] = *reinterpret_cast<const u64*>(a + j * KC + (k2 << 1));
            #pragma unroll
            for (int g = 0; g < 4; g++) {
                u64 wp = *reinterpret_cast<const u64*>(w2 + k2 * 128 + g * 32);
                #pragma unroll
                for (int j = 0; j < RW; j++)
                    ffma2(acc[j][g], ap[j], wp);
            }
        }
    }

    // --- combine k-halves (xch overlays stage 2 W region; quiescent since c=5) ---
    float* xch = (float*)(smem + 2 * STAGE_BYTES);
    if (w >= 8) {
        #pragma unroll
        for (int j = 0; j < RW; j++)
            #pragma unroll
            for (int g = 0; g < 4; g++)
                xch[(((w - 8) * RW) + j) * 128 + g * 32 + hc] = fold2(acc[j][g]);
    }
    __syncthreads();
    if (w < 8) {
        const int hcol = nh0 + hc;
        const float bi = bias[hcol];
        const float bj = bias[256 + hcol];
        const float bf = bias[512 + hcol];
        const float bo = bias[768 + hcol];
        #pragma unroll
        for (int j = 0; j < RW; j++) {
            const int row = w * RW + j;
            const int ci  = row >> 4;
            const int bb  = row & 15;
            const int l   = l_base + ci;
            if (l <= l_hi) {
                const int t    = d - l;
                const int sidx = (l * BB + bb) * HH + hcol;
                const float* xr = &xch[(w * RW + j) * 128 + hc];
                float zi = fold2(acc[j][0]) + xr[0]  + bi;
                float zj = fold2(acc[j][1]) + xr[32] + bj;
                float zf = fold2(acc[j][2]) + xr[64] + bf;
                float zo = fold2(acc[j][3]) + xr[96] + bo;
                float cold = g_c[sidx];
                float ncv  = sig_(zf + 1.0f) * cold + sig_(zi) * tanh_(zj);
                float nhv  = sig_(zo) * tanh_(ncv);
                g_c[sidx]  = ncv;
                hout[sidx] = nhv;
                if (l == LL - 1) out[(bb * TT + t) * HH + hcol] = nhv;
            }
        }
    }
}

__global__ void __launch_bounds__(NTHREADS, 1)
lstm_kernel(const float* __restrict__ x, const float* __restrict__ bias,
            float* __restrict__ out) {
    extern __shared__ __align__(16) char smem[];
    const int tid = threadIdx.x;
    const int G   = gridDim.x;
    const uint32_t sbase = (uint32_t)__cvta_generic_to_shared(smem);

    // --- prologue: prefetch W chunks 0,1 for d=0 (ntiles=8) ---
    {
        const bool act = (blockIdx.x < 8);
        if (act) issueW(sbase, blockIdx.x & 7, 0, 0, tid);
        cpcommit();
        if (act) issueW(sbase, blockIdx.x & 7, 1, 1, tid);
        cpcommit();
    }

    for (int d = 0; d < NDIAG; d++) {
        const int l_lo = (d - (TT - 1) > 0) ? d - (TT - 1) : 0;
        const int l_hi = (d < LL - 1) ? d : LL - 1;
        const int n    = l_hi - l_lo + 1;
        const int CG   = (n + 17) / 18;          // 1..4 cells per M-tile
        const int ngroups = (n + CG - 1) / CG;
        const int ntiles  = ngroups << 3;        // <=144
        const float* hin  = g_h[(d + 1) & 1];
        float*       hout = g_h[d & 1];

        if ((int)blockIdx.x < ntiles) {
            const int tile = blockIdx.x;
            if      (CG == 4) tile_body<4>(smem, x, bias, out, hin, hout, d, l_lo, l_hi, tile);
            else if (CG == 3) tile_body<3>(smem, x, bias, out, hin, hout, d, l_lo, l_hi, tile);
            else if (CG == 2) tile_body<2>(smem, x, bias, out, hin, hout, d, l_lo, l_hi, tile);
            else              tile_body<1>(smem, x, bias, out, hin, hout, d, l_lo, l_hi, tile);
        }

        if (d < NDIAG - 1) {
            // --- cross-barrier W prefetch for next diagonal (W is state-independent) ---
            const int d2    = d + 1;
            const int l_lo2 = (d2 - (TT - 1) > 0) ? d2 - (TT - 1) : 0;
            const int l_hi2 = (d2 < LL - 1) ? d2 : LL - 1;
            const int n2    = l_hi2 - l_lo2 + 1;
            const int CG2   = (n2 + 17) / 18;
            const int ntiles2 = ((n2 + CG2 - 1) / CG2) << 3;
            const bool actN = ((int)blockIdx.x < ntiles2);
            if (actN) issueW(sbase, blockIdx.x & 7, 0, 0, tid);
            cpcommit();
            if (actN) issueW(sbase, blockIdx.x & 7, 1, 1, tid);
            cpcommit();

            // --- grid-wide barrier (release + L1 invalidate via membar.gpu) ---
            __threadfence();
            __syncthreads();
            if (tid == 0) {
                unsigned target = (unsigned)G * (unsigned)(d + 1);
                atomicAdd(&g_bar, 1u);
                while (*((volatile unsigned*)&g_bar) < target) { }
            }
            __syncthreads();
        }
    }
}

extern "C" void kernel_launch(void* const* d_in, const int* in_sizes, int n_in,
                              void* d_out, int out_size) {
    const float* x    = (const float*)d_in[0];   // (B, T, H)
    const float* init = (const float*)d_in[1];   // (L, 2, B, H)
    const float* W    = (const float*)d_in[2];   // (2H, 4H)
    const float* bias = (const float*)d_in[3];   // (4H,)
    float* out        = (float*)d_out;           // (B, T, H)

    cudaFuncSetAttribute(lstm_kernel, cudaFuncAttributeMaxDynamicSharedMemorySize, SMEM_TOTAL);
    init_kernel<<<(LL * BB * HH + 255) / 256, 256>>>(init);
    prep_kernel<<<(8 * 8 * 32 * 128 + 255) / 256, 256>>>(W);
    lstm_kernel<<<GRID, NTHREADS, SMEM_TOTAL>>>(x, bias, out);
}